// round 14
// baseline (speedup 1.0000x reference)
#include <cuda_runtime.h>
#include <cuda_fp16.h>

// ---------------- problem constants ----------------
#define NBLK 6
#define DF   45
#define DM   1035
#define MROWS 64           // rows per CTA (two independent 32-row groups)
#define NTHR 256

#define Z16S 72            // fp16 z row stride (halves), 64 cols (2 k-slabs)
#define AS16 264           // fp16 act row stride (halves), 256 cols (8 k-slabs)
#define FN   192           // f-chunk cols (8 features x 24)
#define NCHK 6             // f chunks
#define PSTR 202           // fp16 params row stride (halves) within group sub-block
#define GHALF 16896        // bytes per group half of the region (32*264*2)

// smem byte offsets (total 78848 -> 2 CTAs/SM)
#define OB_Z16  0                     // [64][72] fp16 = 9216
#define OB_LDP  9216                  // [256] float2 = 2048
#define OB_ACTA 11264                 // [64][264] fp16 = 33792
#define OB_REGN 45056                 // actB [64][264] fp16 ALIASED with per-group par strips
#define SMEM_BYTES 78848

#define GBAR(id) asm volatile("bar.sync %0, 128;" :: "r"(id) : "memory")

// ---------------- device weight images (masked, permuted, k-interleaved, LDG-fragment layout) ----------------
__device__ __half g_W0p[NBLK * 2 * 256 * 32];
__device__ __half g_Whp[NBLK * 2 * 8 * 256 * 32];
__device__ __half g_Wfp[NBLK * NCHK * 8 * FN * 32];
__device__ float  g_bhp[NBLK * 2 * 256];     // degree-permuted hidden biases

// ---------------- helpers ----------------
__device__ __forceinline__ void mma16(float* d, unsigned a0, unsigned a1, unsigned a2, unsigned a3,
                                      unsigned b0, unsigned b1) {
    asm volatile("mma.sync.aligned.m16n8k16.row.col.f32.f16.f16.f32 "
        "{%0,%1,%2,%3},{%4,%5,%6,%7},{%8,%9},{%0,%1,%2,%3};"
        : "+f"(d[0]), "+f"(d[1]), "+f"(d[2]), "+f"(d[3])
        : "r"(a0), "r"(a1), "r"(a2), "r"(a3), "r"(b0), "r"(b1));
}
// phys column of logical k within interleaved 32-k slabs (A-side layout)
__device__ __forceinline__ int acol(int c) {
    int s = c >> 5, k32 = c & 31, step = k32 >> 4, w16 = k32 & 15;
    int hi = w16 >> 3, t = (w16 & 7) >> 1, q = hi * 2 + (w16 & 1);
    return s * 32 + t * 8 + step * 4 + q;
}
// logical k from slab s, phys pos p (<32)
__device__ __forceinline__ int kfp2(int s, int p) {
    int t = p >> 3, rem = p & 7, step = rem >> 2, q = rem & 3;
    int w16 = (q < 2) ? (2 * t + q) : (8 + 2 * t + (q - 2));
    return s * 32 + step * 16 + w16;
}
// degree-sort inverse: original hidden unit for sorted index j
__device__ __forceinline__ int invp(int j) {
    return (j < 216) ? (j / 6 + 44 * (j % 6))
                     : (36 + (j - 216) / 5 + 44 * ((j - 216) % 5));
}

// ---------------- prep kernels ----------------
__global__ void prep_w0(const float* __restrict__ W0, const float* __restrict__ Wc,
                        const float* __restrict__ b0, const float* __restrict__ bc) {
    int idx = blockIdx.x * blockDim.x + threadIdx.x;
    if (idx >= NBLK * 2 * 256 * 32) return;
    int p = idx & 31, n = (idx >> 5) & 255, s = (idx >> 13) & 1, b = idx >> 14;
    int k = kfp2(s, p);
    int o = invp(n);
    float v = 0.0f;
    if (k < DF)       v = ((o % 44) >= k) ? W0[(b * 256 + o) * DF + k] : 0.0f;
    else if (k == 45) v = Wc[b * 256 + o];
    else if (k == 46) v = b0[b * 256 + o] + bc[b * 256 + o];
    g_W0p[idx] = __float2half(v);
}
__global__ void prep_wh(const float* __restrict__ Wh) {
    int idx = blockIdx.x * blockDim.x + threadIdx.x;
    if (idx >= NBLK * 2 * 8 * 256 * 32) return;
    int p = idx & 31, n = (idx >> 5) & 255, s = (idx >> 13) & 7, bl = idx >> 16;
    int o = invp(n);
    int kk = invp(kfp2(s, p));
    float v = ((o % 44) >= (kk % 44)) ? Wh[((size_t)(bl * 256 + o)) * 256 + kk] : 0.0f;
    g_Whp[idx] = __float2half(v);
}
__global__ void prep_wf(const float* __restrict__ Wf) {
    int idx = blockIdx.x * blockDim.x + threadIdx.x;
    if (idx >= NBLK * NCHK * 8 * FN * 32) return;
    int p = idx & 31, n = (idx >> 5) % FN, s = (idx / (FN * 32)) & 7;
    int ch = (idx / (FN * 32 * 8)) % NCHK, b = idx / (FN * 32 * 8 * NCHK);
    int kk = invp(kfp2(s, p));
    int fl = n / 24, i = n % 24, f = ch * 8 + fl;
    float v = 0.0f;
    if (i < 23 && f < DF && f > (kk % 44))
        v = Wf[((size_t)(b * DM + f * 23 + i)) * 256 + kk];
    g_Wfp[idx] = __float2half(v);
}
__global__ void prep_bh(const float* __restrict__ bh) {
    int idx = blockIdx.x * blockDim.x + threadIdx.x;
    if (idx >= NBLK * 2 * 256) return;
    int n = idx & 255, bl = idx >> 8;
    g_bhp[idx] = bh[bl * 256 + invp(n)];
}

// ---------------- L0 dense: [64 x 256] = z16[64 x 64] * W0[64 x 256]; group-local ----------------
__device__ __forceinline__ void dense0(const __half* __restrict__ Wg,
                                       const __half* __restrict__ z16,
                                       __half* __restrict__ dst,
                                       int wm, int wn, int lane, int barid)
{
    const int g = lane >> 2, t = lane & 3;

    float acc[2][8][4];
    #pragma unroll
    for (int mt = 0; mt < 2; mt++)
        #pragma unroll
        for (int nt = 0; nt < 8; nt++)
            acc[mt][nt][0] = acc[mt][nt][1] = acc[mt][nt][2] = acc[mt][nt][3] = 0.0f;

    GBAR(barid);   // entry: group's spline z16 writes / group's prior actA readers arrived

    const __half* aprow = z16 + (wm * 32 + g) * Z16S + t * 8;
    const __half* bbase = Wg + ((size_t)(wn * 64 + g)) * 32 + t * 8;

    #pragma unroll
    for (int s = 0; s < 2; s++) {
        uint4 Av[4];
        {
            const __half* ap = aprow + s * 32;
            Av[0] = *(const uint4*)ap;
            Av[1] = *(const uint4*)(ap + 8 * Z16S);
            Av[2] = *(const uint4*)(ap + 16 * Z16S);
            Av[3] = *(const uint4*)(ap + 24 * Z16S);
        }
        const __half* bp = bbase + (size_t)s * (256 * 32);
        #pragma unroll
        for (int nt = 0; nt < 8; nt++) {
            uint4 Bv = *(const uint4*)(bp + nt * (8 * 32));
            mma16(acc[0][nt], Av[0].x, Av[1].x, Av[0].y, Av[1].y, Bv.x, Bv.y);
            mma16(acc[1][nt], Av[2].x, Av[3].x, Av[2].y, Av[3].y, Bv.x, Bv.y);
            mma16(acc[0][nt], Av[0].z, Av[1].z, Av[0].w, Av[1].w, Bv.z, Bv.w);
            mma16(acc[1][nt], Av[2].z, Av[3].z, Av[2].w, Av[3].w, Bv.z, Bv.w);
        }
    }
    #pragma unroll
    for (int nt = 0; nt < 8; nt++) {
        int c0 = wn * 64 + nt * 8 + 2 * t;
        int pos = acol(c0);
        #pragma unroll
        for (int mt = 0; mt < 2; mt++) {
            int r0 = wm * 32 + mt * 16 + g;
            *(half2*)(dst + r0 * AS16 + pos)       = __floats2half2_rn(acc[mt][nt][0], acc[mt][nt][1]);
            *(half2*)(dst + (r0 + 8) * AS16 + pos) = __floats2half2_rn(acc[mt][nt][2], acc[mt][nt][3]);
        }
    }
}

// ---------------- hidden impl (compile-time slab counts), OUT-OF-PLACE, group-local ----------------
template<int NS0, int NS1>
__device__ __forceinline__ void hidden_impl(const __half* __restrict__ Wg,
                                            const float* __restrict__ biasP,
                                            const __half* __restrict__ src,
                                            __half* __restrict__ dst,
                                            int wm, int wj, int lane)
{
    const int g = lane >> 2, t = lane & 3;

    float acc[2][2][4][4];
    #pragma unroll
    for (int ti = 0; ti < 2; ti++)
        #pragma unroll
        for (int mt = 0; mt < 2; mt++)
            #pragma unroll
            for (int j = 0; j < 4; j++)
                acc[ti][mt][j][0] = acc[ti][mt][j][1] = acc[ti][mt][j][2] = acc[ti][mt][j][3] = 0.0f;

    const __half* aprow = src + (wm * 32 + g) * AS16 + t * 8;

    #pragma unroll
    for (int ti = 0; ti < 2; ti++) {
        const int tile = ti ? (7 - wj) : wj;
        const int NS = ti ? NS1 : NS0;
        const __half* bbase = Wg + ((size_t)(tile * 32 + g)) * 32 + t * 8;
        #pragma unroll
        for (int s = 0; s < NS; s++) {
            uint4 Av[4];
            {
                const __half* ap = aprow + s * 32;
                Av[0] = *(const uint4*)ap;
                Av[1] = *(const uint4*)(ap + 8 * AS16);
                Av[2] = *(const uint4*)(ap + 16 * AS16);
                Av[3] = *(const uint4*)(ap + 24 * AS16);
            }
            const __half* bp = bbase + (size_t)s * (256 * 32);
            #pragma unroll
            for (int j = 0; j < 4; j++) {
                uint4 Bv = *(const uint4*)(bp + j * (8 * 32));
                mma16(acc[ti][0][j], Av[0].x, Av[1].x, Av[0].y, Av[1].y, Bv.x, Bv.y);
                mma16(acc[ti][1][j], Av[2].x, Av[3].x, Av[2].y, Av[3].y, Bv.x, Bv.y);
                mma16(acc[ti][0][j], Av[0].z, Av[1].z, Av[0].w, Av[1].w, Bv.z, Bv.w);
                mma16(acc[ti][1][j], Av[2].z, Av[3].z, Av[2].w, Av[3].w, Bv.z, Bv.w);
            }
        }
    }
    #pragma unroll
    for (int ti = 0; ti < 2; ti++) {
        const int tile = ti ? (7 - wj) : wj;
        #pragma unroll
        for (int j = 0; j < 4; j++) {
            int c0 = tile * 32 + j * 8 + 2 * t;
            int pos = acol(c0);
            float2 bb = *(const float2*)(biasP + c0);
            #pragma unroll
            for (int mt = 0; mt < 2; mt++) {
                int r0 = wm * 32 + mt * 16 + g;
                float v0 = fmaxf(acc[ti][mt][j][0] + bb.x, 0.0f);
                float v1 = fmaxf(acc[ti][mt][j][1] + bb.y, 0.0f);
                float v2 = fmaxf(acc[ti][mt][j][2] + bb.x, 0.0f);
                float v3 = fmaxf(acc[ti][mt][j][3] + bb.y, 0.0f);
                *(half2*)(dst + r0 * AS16 + pos)       = __floats2half2_rn(v0, v1);
                *(half2*)(dst + (r0 + 8) * AS16 + pos) = __floats2half2_rn(v2, v3);
            }
        }
    }
}

__device__ __forceinline__ void hidden_dense(const __half* __restrict__ Wg,
                                             const float* __restrict__ biasP,
                                             const __half* __restrict__ src,
                                             __half* __restrict__ dst,
                                             int wm, int wj, int lane, int barid)
{
    GBAR(barid);   // entry: group's src writers / group's prior dst readers arrived
    switch (wj) {                                     // SL pairs: (2,8) (3,8) (3,6) (5,6)
        case 0: hidden_impl<2, 8>(Wg, biasP, src, dst, wm, 0, lane); break;
        case 1: hidden_impl<3, 8>(Wg, biasP, src, dst, wm, 1, lane); break;
        case 2: hidden_impl<3, 6>(Wg, biasP, src, dst, wm, 2, lane); break;
        default: hidden_impl<5, 6>(Wg, biasP, src, dst, wm, 3, lane); break;
    }
}

// ---------------- f-layer chunk MMA + epilogue to warp's PRIVATE par strip (compile-time slabs) ----------------
template<int NS>
__device__ __forceinline__ void f_chunk(const __half* __restrict__ Wg,
                                        const __half* __restrict__ act,
                                        __half* __restrict__ parg,
                                        int wm, int wn, int lane)
{
    const int g = lane >> 2, t = lane & 3;

    float acc[2][6][4];
    #pragma unroll
    for (int mt = 0; mt < 2; mt++)
        #pragma unroll
        for (int nt = 0; nt < 6; nt++)
            acc[mt][nt][0] = acc[mt][nt][1] = acc[mt][nt][2] = acc[mt][nt][3] = 0.0f;

    const __half* aprow = act + (wm * 32 + g) * AS16 + t * 8;
    const __half* bbase = Wg + ((size_t)(wn * 48 + g)) * 32 + t * 8;

    #pragma unroll
    for (int s = 0; s < NS; s++) {
        uint4 Av[4];
        {
            const __half* ap = aprow + s * 32;
            Av[0] = *(const uint4*)ap;
            Av[1] = *(const uint4*)(ap + 8 * AS16);
            Av[2] = *(const uint4*)(ap + 16 * AS16);
            Av[3] = *(const uint4*)(ap + 24 * AS16);
        }
        const __half* bp = bbase + (size_t)s * (FN * 32);
        #pragma unroll
        for (int nt = 0; nt < 6; nt++) {
            uint4 Bv = *(const uint4*)(bp + nt * (8 * 32));
            mma16(acc[0][nt], Av[0].x, Av[1].x, Av[0].y, Av[1].y, Bv.x, Bv.y);
            mma16(acc[1][nt], Av[2].x, Av[3].x, Av[2].y, Av[3].y, Bv.x, Bv.y);
            mma16(acc[0][nt], Av[0].z, Av[1].z, Av[0].w, Av[1].w, Bv.z, Bv.w);
            mma16(acc[1][nt], Av[2].z, Av[3].z, Av[2].w, Av[3].w, Bv.z, Bv.w);
        }
    }
    #pragma unroll
    for (int nt = 0; nt < 6; nt++) {
        int c0 = wn * 48 + nt * 8 + 2 * t;
        #pragma unroll
        for (int mt = 0; mt < 2; mt++) {
            int rl = mt * 16 + g;      // group-local row
            *(half2*)(parg + rl * PSTR + c0)       = __floats2half2_rn(acc[mt][nt][0], acc[mt][nt][1]);
            *(half2*)(parg + (rl + 8) * PSTR + c0) = __floats2half2_rn(acc[mt][nt][2], acc[mt][nt][3]);
        }
    }
}

// ---------------- rational-quadratic spline, K=8 bins ----------------
__device__ __forceinline__ float2 rq_spline(const float* __restrict__ p, float x)
{
    const float TAIL = 13.815510557964274f;
    const float INVS = 0.0625f;
    bool inside = (x >= -TAIL) && (x <= TAIL);
    float xc = fminf(fmaxf(x, -TAIL), TAIL);

    float ew[8], eh[8];
    float sw = 0.0f, sh = 0.0f;
    #pragma unroll
    for (int i = 0; i < 8; i++) {
        ew[i] = __expf(p[i] * INVS);      sw += ew[i];
        eh[i] = __expf(p[8 + i] * INVS);  sh += eh[i];
    }
    float iw = 1.0f / sw, ih = 1.0f / sh;

    float d[9]; d[0] = 1.0f; d[8] = 1.0f;
    #pragma unroll
    for (int i = 0; i < 7; i++) {
        float u = p[16 + i];
        d[i + 1] = 1e-3f + __logf(1.0f + __expf(u));   // |u| small: stable & exact enough
    }

    float cumw = 0.0f, cumh = 0.0f, cwl = -TAIL, chl = -TAIL;
    float bcwl = -TAIL, bw = 1.0f, bchl = -TAIL, bh2 = 1.0f, bd0 = 1.0f, bd1 = 1.0f;
    #pragma unroll
    for (int i = 0; i < 8; i++) {
        cumw += 1e-3f + 0.992f * (ew[i] * iw);
        cumh += 1e-3f + 0.992f * (eh[i] * ih);
        float cwr = (i == 7) ? TAIL : fmaf(2.0f * TAIL, cumw, -TAIL);
        float chr = (i == 7) ? TAIL : fmaf(2.0f * TAIL, cumh, -TAIL);
        if (xc >= cwl) { bcwl = cwl; bw = cwr - cwl; bchl = chl; bh2 = chr - chl; bd0 = d[i]; bd1 = d[i + 1]; }
        cwl = cwr; chl = chr;
    }

    float th  = (xc - bcwl) / bw;
    float th1 = th * (1.0f - th);
    float dl  = bh2 / bw;
    float den = dl + (bd0 + bd1 - 2.0f * dl) * th1;
    float y   = bchl + bh2 * (dl * th * th + bd0 * th1) / den;
    float omt = 1.0f - th;
    float ln  = dl * dl * (bd1 * th * th + 2.0f * dl * th1 + bd0 * omt * omt);
    float lad = __logf(ln) - 2.0f * __logf(den);
    float2 r; r.x = inside ? y : x; r.y = inside ? lad : 0.0f;
    return r;
}

// spline pass for one chunk: 2 features per thread, z in registers
__device__ __forceinline__ void spline_pass(int ch, const float* __restrict__ bfb,
                                            const __half* __restrict__ parg,
                                            __half* __restrict__ z16,
                                            int wm, int wn, int lane,
                                            float* __restrict__ zloc, float& ldacc)
{
    const int r = wm * 32 + lane;
    #pragma unroll
    for (int q = 0; q < 2; q++) {
        int fl = 2 * wn + q;
        int f = ch * 8 + fl;
        if (f < DF) {
            float p[23];
            const float* bfp = bfb + f * 23;
            const __half* pp = parg + lane * PSTR + fl * 24;
            #pragma unroll
            for (int i = 0; i < 23; i++)
                p[i] = __half2float(pp[i]) + bfp[i];
            float2 yr = rq_spline(p, zloc[ch * 2 + q]);
            zloc[ch * 2 + q] = yr.x;
            z16[r * Z16S + acol(f)] = __float2half(yr.x);
            ldacc += yr.y;
        }
    }
}

// ---------------- main fused kernel ----------------
__global__ void __launch_bounds__(NTHR, 2)
maf_kernel(const float* __restrict__ x, const float* __restrict__ cond,
           const float* __restrict__ bf,
           float* __restrict__ out)
{
    extern __shared__ char smc[];
    __half* z16  = (__half*)(smc + OB_Z16);   // [64][72]
    float2* ldp  = (float2*)(smc + OB_LDP);   // [256] (ld, sum z^2)
    __half* actA = (__half*)(smc + OB_ACTA);  // [64][264]
    __half* actB = (__half*)(smc + OB_REGN);  // [64][264]; per-group halves alias par strips

    const int tid  = threadIdx.x;
    const int lane = tid & 31, w = tid >> 5;
    const int wm = w & 1, wn = w >> 1;        // group wm; within-group warp wn (0..3)
    const int barid = 1 + wm;
    const int gl = wn * 32 + lane;            // group-local thread index 0..127
    const int row0 = blockIdx.x * MROWS;
    const int r = wm * 32 + lane;
    __half* parg = (__half*)(smc + OB_REGN + wm * GHALF);   // group par strip (rows local 0..31)
    float ldacc = 0.0f;
    float zloc[12];

    // per-thread z registers for the 12 owned features
    #pragma unroll
    for (int ch = 0; ch < NCHK; ch++)
        #pragma unroll
        for (int q = 0; q < 2; q++) {
            int f = ch * 8 + 2 * wn + q;
            zloc[ch * 2 + q] = (f < DF) ? x[(row0 + r) * DF + f] : 0.0f;
        }
    // group-local z16 init (rows wm*32 .. wm*32+31)
    for (int i = gl; i < 32 * 64; i += 128) {
        int rl = i >> 6, f = i & 63, rr = wm * 32 + rl;
        float v = (f < DF) ? x[(row0 + rr) * DF + f]
                 : (f == 45) ? cond[row0 + rr]
                 : (f == 46) ? 1.0f : 0.0f;
        z16[rr * Z16S + acol(f)] = __float2half(v);
    }
    // ordering via dense0 entry group barrier

    for (int b = 0; b < NBLK; b++) {
        dense0(g_W0p + (size_t)b * 2 * 256 * 32, z16, actA, wm, wn, lane, barid);
        hidden_dense(g_Whp + (size_t)(b * 2 + 0) * 8 * 256 * 32, g_bhp + (b * 2 + 0) * 256,
                     actA, actB, wm, wn, lane, barid);
        hidden_dense(g_Whp + (size_t)(b * 2 + 1) * 8 * 256 * 32, g_bhp + (b * 2 + 1) * 256,
                     actB, actA, wm, wn, lane, barid);

        GBAR(barid);   // group: actB reads done (hidden2), actA writes visible -> par may alias actB
        const __half* Wfb = g_Wfp + (size_t)(b * NCHK) * 8 * FN * 32;
        const float*  bfb = bf + b * DM;

#define F_STEP(CH, NS) do {                                                     \
            f_chunk<NS>(Wfb + (size_t)(CH) * 8 * FN * 32, actA, parg, wm, wn, lane); \
            __syncwarp();                                                       \
            spline_pass(CH, bfb, parg, z16, wm, wn, lane, zloc, ldacc);         \
            __syncwarp();                                                       \
        } while (0)

        F_STEP(0, 2); F_STEP(1, 3); F_STEP(2, 5);
        F_STEP(3, 6); F_STEP(4, 8); F_STEP(5, 8);
#undef F_STEP
    }

    float sacc = 0.0f;
    #pragma unroll
    for (int i = 0; i < 12; i++) sacc = fmaf(zloc[i], zloc[i], sacc);
    ldp[tid] = make_float2(ldacc, sacc);
    __syncthreads();
    if (tid < MROWS) {     // tid = wm*32+lane exactly maps to row r=tid
        float2 v0 = ldp[tid], v1 = ldp[tid + 64], v2 = ldp[tid + 128], v3 = ldp[tid + 192];
        float ld = v0.x + v1.x + v2.x + v3.x;
        float s  = v0.y + v1.y + v2.y + v3.y;
        out[row0 + tid] = -0.5f * s - 41.35223399420827f + ld;
    }
}

// ---------------- launch ----------------
extern "C" void kernel_launch(void* const* d_in, const int* in_sizes, int n_in,
                              void* d_out, int out_size) {
    const float* x    = (const float*)d_in[0];
    const float* cond = (const float*)d_in[1];
    const float* W0   = (const float*)d_in[2];
    const float* b0   = (const float*)d_in[3];
    const float* Wc   = (const float*)d_in[4];
    const float* bc   = (const float*)d_in[5];
    const float* Wh   = (const float*)d_in[6];
    const float* bh   = (const float*)d_in[7];
    const float* Wf   = (const float*)d_in[8];
    const float* bf   = (const float*)d_in[9];
    float* out = (float*)d_out;
    const int B = in_sizes[0] / DF;

    prep_w0<<<(NBLK * 2 * 256 * 32 + 255) / 256, 256>>>(W0, Wc, b0, bc);
    prep_wh<<<(NBLK * 2 * 8 * 256 * 32 + 255) / 256, 256>>>(Wh);
    prep_wf<<<(NBLK * NCHK * 8 * FN * 32 + 255) / 256, 256>>>(Wf);
    prep_bh<<<(NBLK * 2 * 256 + 255) / 256, 256>>>(bh);

    cudaFuncSetAttribute(maf_kernel, cudaFuncAttributeMaxDynamicSharedMemorySize, SMEM_BYTES);
    maf_kernel<<<B / MROWS, NTHR, SMEM_BYTES>>>(x, cond, bf, out);
}

// round 15
// speedup vs baseline: 1.0965x; 1.0965x over previous
#include <cuda_runtime.h>
#include <cuda_fp16.h>

// ---------------- problem constants ----------------
#define NBLK 6
#define DF   45
#define DM   1035
#define MROWS 64           // rows per CTA (two independent 32-row groups)
#define NTHR 256

#define Z32S 49            // fp32 z row stride
#define Z16S 72            // fp16 z row stride (halves), 64 cols (2 k-slabs)
#define AS16 264           // fp16 act row stride (halves), 256 cols (8 k-slabs)
#define FN   192           // f-chunk cols (8 features x 24)
#define NCHK 6             // f chunks
#define PSTR 202           // fp16 params row stride (halves) within group sub-block
#define GHALF 16896        // bytes per group half of the region (32*264*2)

// smem byte offsets (total 90368 -> 2 CTAs/SM)
#define OB_Z32  0
#define OB_Z16  12544                 // 64*49*4
#define OB_LDP  (OB_Z16 + 9216)       // [256] fp32
#define OB_ACTA (OB_LDP + 1024)
#define OB_REGN (OB_ACTA + 33792)     // actB [64][264] fp16 ALIASED with per-group par strips
#define SMEM_BYTES (OB_REGN + 33792)  // 90368

// per-N-tile k-slab bounds (degree-sorted hidden): SL[j] nibble-packed
#define SL_PACK 0x88665332u
// per-f-chunk k-slab bounds {2,3,5,6,8,8}
#define FSL_PACK 0x00886532u

#define GBAR(id) asm volatile("bar.sync %0, 128;" :: "r"(id) : "memory")

// ---------------- device weight images (masked, permuted, k-interleaved, LDG-fragment layout) ----------------
__device__ __half g_W0p[NBLK * 2 * 256 * 32];
__device__ __half g_Whp[NBLK * 2 * 8 * 256 * 32];
__device__ __half g_Wfp[NBLK * NCHK * 8 * FN * 32];
__device__ float  g_bhp[NBLK * 2 * 256];     // degree-permuted hidden biases

// ---------------- helpers ----------------
__device__ __forceinline__ void mma16(float* d, unsigned a0, unsigned a1, unsigned a2, unsigned a3,
                                      unsigned b0, unsigned b1) {
    asm volatile("mma.sync.aligned.m16n8k16.row.col.f32.f16.f16.f32 "
        "{%0,%1,%2,%3},{%4,%5,%6,%7},{%8,%9},{%0,%1,%2,%3};"
        : "+f"(d[0]), "+f"(d[1]), "+f"(d[2]), "+f"(d[3])
        : "r"(a0), "r"(a1), "r"(a2), "r"(a3), "r"(b0), "r"(b1));
}
// phys column of logical k within interleaved 32-k slabs (A-side layout)
__device__ __forceinline__ int acol(int c) {
    int s = c >> 5, k32 = c & 31, step = k32 >> 4, w16 = k32 & 15;
    int hi = w16 >> 3, t = (w16 & 7) >> 1, q = hi * 2 + (w16 & 1);
    return s * 32 + t * 8 + step * 4 + q;
}
// logical k from slab s, phys pos p (<32)
__device__ __forceinline__ int kfp2(int s, int p) {
    int t = p >> 3, rem = p & 7, step = rem >> 2, q = rem & 3;
    int w16 = (q < 2) ? (2 * t + q) : (8 + 2 * t + (q - 2));
    return s * 32 + step * 16 + w16;
}
// degree-sort inverse: original hidden unit for sorted index j
__device__ __forceinline__ int invp(int j) {
    return (j < 216) ? (j / 6 + 44 * (j % 6))
                     : (36 + (j - 216) / 5 + 44 * ((j - 216) % 5));
}

// ---------------- prep kernels ----------------
__global__ void prep_w0(const float* __restrict__ W0, const float* __restrict__ Wc,
                        const float* __restrict__ b0, const float* __restrict__ bc) {
    int idx = blockIdx.x * blockDim.x + threadIdx.x;
    if (idx >= NBLK * 2 * 256 * 32) return;
    int p = idx & 31, n = (idx >> 5) & 255, s = (idx >> 13) & 1, b = idx >> 14;
    int k = kfp2(s, p);
    int o = invp(n);
    float v = 0.0f;
    if (k < DF)       v = ((o % 44) >= k) ? W0[(b * 256 + o) * DF + k] : 0.0f;
    else if (k == 45) v = Wc[b * 256 + o];
    else if (k == 46) v = b0[b * 256 + o] + bc[b * 256 + o];
    g_W0p[idx] = __float2half(v);
}
__global__ void prep_wh(const float* __restrict__ Wh) {
    int idx = blockIdx.x * blockDim.x + threadIdx.x;
    if (idx >= NBLK * 2 * 8 * 256 * 32) return;
    int p = idx & 31, n = (idx >> 5) & 255, s = (idx >> 13) & 7, bl = idx >> 16;
    int o = invp(n);
    int kk = invp(kfp2(s, p));
    float v = ((o % 44) >= (kk % 44)) ? Wh[((size_t)(bl * 256 + o)) * 256 + kk] : 0.0f;
    g_Whp[idx] = __float2half(v);
}
__global__ void prep_wf(const float* __restrict__ Wf) {
    int idx = blockIdx.x * blockDim.x + threadIdx.x;
    if (idx >= NBLK * NCHK * 8 * FN * 32) return;
    int p = idx & 31, n = (idx >> 5) % FN, s = (idx / (FN * 32)) & 7;
    int ch = (idx / (FN * 32 * 8)) % NCHK, b = idx / (FN * 32 * 8 * NCHK);
    int kk = invp(kfp2(s, p));
    int fl = n / 24, i = n % 24, f = ch * 8 + fl;
    float v = 0.0f;
    if (i < 23 && f < DF && f > (kk % 44))
        v = Wf[((size_t)(b * DM + f * 23 + i)) * 256 + kk];
    g_Wfp[idx] = __float2half(v);
}
__global__ void prep_bh(const float* __restrict__ bh) {
    int idx = blockIdx.x * blockDim.x + threadIdx.x;
    if (idx >= NBLK * 2 * 256) return;
    int n = idx & 255, bl = idx >> 8;
    g_bhp[idx] = bh[bl * 256 + invp(n)];
}

// ---------------- L0 dense: [64 x 256] = z16[64 x 64] * W0[64 x 256]; group-local ----------------
__device__ __forceinline__ void dense0(const __half* __restrict__ Wg,
                                       const __half* __restrict__ z16,
                                       __half* __restrict__ dst,
                                       int wm, int wn, int lane, int barid)
{
    const int g = lane >> 2, t = lane & 3;

    float acc[2][8][4];
    #pragma unroll
    for (int mt = 0; mt < 2; mt++)
        #pragma unroll
        for (int nt = 0; nt < 8; nt++)
            acc[mt][nt][0] = acc[mt][nt][1] = acc[mt][nt][2] = acc[mt][nt][3] = 0.0f;

    GBAR(barid);   // entry: group's spline z16 writes / group's prior actA readers arrived

    const __half* aprow = z16 + (wm * 32 + g) * Z16S + t * 8;
    const __half* bbase = Wg + ((size_t)(wn * 64 + g)) * 32 + t * 8;

    #pragma unroll
    for (int s = 0; s < 2; s++) {
        uint4 Av[4];
        {
            const __half* ap = aprow + s * 32;
            Av[0] = *(const uint4*)ap;
            Av[1] = *(const uint4*)(ap + 8 * Z16S);
            Av[2] = *(const uint4*)(ap + 16 * Z16S);
            Av[3] = *(const uint4*)(ap + 24 * Z16S);
        }
        const __half* bp = bbase + (size_t)s * (256 * 32);
        #pragma unroll
        for (int nt = 0; nt < 8; nt++) {
            uint4 Bv = *(const uint4*)(bp + nt * (8 * 32));
            mma16(acc[0][nt], Av[0].x, Av[1].x, Av[0].y, Av[1].y, Bv.x, Bv.y);
            mma16(acc[1][nt], Av[2].x, Av[3].x, Av[2].y, Av[3].y, Bv.x, Bv.y);
            mma16(acc[0][nt], Av[0].z, Av[1].z, Av[0].w, Av[1].w, Bv.z, Bv.w);
            mma16(acc[1][nt], Av[2].z, Av[3].z, Av[2].w, Av[3].w, Bv.z, Bv.w);
        }
    }
    #pragma unroll
    for (int nt = 0; nt < 8; nt++) {
        int c0 = wn * 64 + nt * 8 + 2 * t;
        int pos = acol(c0);
        #pragma unroll
        for (int mt = 0; mt < 2; mt++) {
            int r0 = wm * 32 + mt * 16 + g;
            *(half2*)(dst + r0 * AS16 + pos)       = __floats2half2_rn(acc[mt][nt][0], acc[mt][nt][1]);
            *(half2*)(dst + (r0 + 8) * AS16 + pos) = __floats2half2_rn(acc[mt][nt][2], acc[mt][nt][3]);
        }
    }
}

// ---------------- hidden dense (degree-sorted, per-warp truncated K), OUT-OF-PLACE, group-local ----------------
__device__ __forceinline__ void hidden_dense(const __half* __restrict__ Wg,
                                             const float* __restrict__ biasP,
                                             const __half* __restrict__ src,
                                             __half* __restrict__ dst,
                                             int wm, int wj, int lane, int barid)
{
    const int g = lane >> 2, t = lane & 3;

    float acc[2][2][4][4];
    #pragma unroll
    for (int ti = 0; ti < 2; ti++)
        #pragma unroll
        for (int mt = 0; mt < 2; mt++)
            #pragma unroll
            for (int j = 0; j < 4; j++)
                acc[ti][mt][j][0] = acc[ti][mt][j][1] = acc[ti][mt][j][2] = acc[ti][mt][j][3] = 0.0f;

    GBAR(barid);   // entry: group's src writers / group's prior dst readers arrived

    const __half* aprow = src + (wm * 32 + g) * AS16 + t * 8;

    #pragma unroll
    for (int ti = 0; ti < 2; ti++) {
        const int tile = ti ? (7 - wj) : wj;
        const int ns = (int)((SL_PACK >> (4 * tile)) & 0xFu);
        const __half* bbase = Wg + ((size_t)(tile * 32 + g)) * 32 + t * 8;
        for (int s = 0; s < ns; s++) {
            uint4 Av[4];
            {
                const __half* ap = aprow + s * 32;
                Av[0] = *(const uint4*)ap;
                Av[1] = *(const uint4*)(ap + 8 * AS16);
                Av[2] = *(const uint4*)(ap + 16 * AS16);
                Av[3] = *(const uint4*)(ap + 24 * AS16);
            }
            const __half* bp = bbase + (size_t)s * (256 * 32);
            #pragma unroll
            for (int j = 0; j < 4; j++) {
                uint4 Bv = *(const uint4*)(bp + j * (8 * 32));
                mma16(acc[ti][0][j], Av[0].x, Av[1].x, Av[0].y, Av[1].y, Bv.x, Bv.y);
                mma16(acc[ti][1][j], Av[2].x, Av[3].x, Av[2].y, Av[3].y, Bv.x, Bv.y);
                mma16(acc[ti][0][j], Av[0].z, Av[1].z, Av[0].w, Av[1].w, Bv.z, Bv.w);
                mma16(acc[ti][1][j], Av[2].z, Av[3].z, Av[2].w, Av[3].w, Bv.z, Bv.w);
            }
        }
    }
    #pragma unroll
    for (int ti = 0; ti < 2; ti++) {
        const int tile = ti ? (7 - wj) : wj;
        #pragma unroll
        for (int j = 0; j < 4; j++) {
            int c0 = tile * 32 + j * 8 + 2 * t;
            int pos = acol(c0);
            float2 bb = *(const float2*)(biasP + c0);
            #pragma unroll
            for (int mt = 0; mt < 2; mt++) {
                int r0 = wm * 32 + mt * 16 + g;
                float v0 = fmaxf(acc[ti][mt][j][0] + bb.x, 0.0f);
                float v1 = fmaxf(acc[ti][mt][j][1] + bb.y, 0.0f);
                float v2 = fmaxf(acc[ti][mt][j][2] + bb.x, 0.0f);
                float v3 = fmaxf(acc[ti][mt][j][3] + bb.y, 0.0f);
                *(half2*)(dst + r0 * AS16 + pos)       = __floats2half2_rn(v0, v1);
                *(half2*)(dst + (r0 + 8) * AS16 + pos) = __floats2half2_rn(v2, v3);
            }
        }
    }
}

// ---------------- f-layer chunk: compute (LDG+HMMA -> regs) and store split ----------------
__device__ __forceinline__ void f_compute(const __half* __restrict__ Wg,
                                          const __half* __restrict__ act,
                                          int wm, int wn, int lane, int ns,
                                          float* __restrict__ acc)   // [48] = [mt][nt][j]
{
    const int g = lane >> 2, t = lane & 3;
    #pragma unroll
    for (int i = 0; i < 48; i++) acc[i] = 0.0f;

    const __half* aprow = act + (wm * 32 + g) * AS16 + t * 8;
    const __half* bbase = Wg + ((size_t)(wn * 48 + g)) * 32 + t * 8;

    for (int s = 0; s < ns; s++) {
        uint4 Av[4];
        {
            const __half* ap = aprow + s * 32;
            Av[0] = *(const uint4*)ap;
            Av[1] = *(const uint4*)(ap + 8 * AS16);
            Av[2] = *(const uint4*)(ap + 16 * AS16);
            Av[3] = *(const uint4*)(ap + 24 * AS16);
        }
        const __half* bp = bbase + (size_t)s * (FN * 32);
        #pragma unroll
        for (int nt = 0; nt < 6; nt++) {
            uint4 Bv = *(const uint4*)(bp + nt * (8 * 32));
            mma16(acc + (0 * 6 + nt) * 4, Av[0].x, Av[1].x, Av[0].y, Av[1].y, Bv.x, Bv.y);
            mma16(acc + (1 * 6 + nt) * 4, Av[2].x, Av[3].x, Av[2].y, Av[3].y, Bv.x, Bv.y);
            mma16(acc + (0 * 6 + nt) * 4, Av[0].z, Av[1].z, Av[0].w, Av[1].w, Bv.z, Bv.w);
            mma16(acc + (1 * 6 + nt) * 4, Av[2].z, Av[3].z, Av[2].w, Av[3].w, Bv.z, Bv.w);
        }
    }
}

__device__ __forceinline__ void f_store(const float* __restrict__ acc,
                                        __half* __restrict__ parg, int wn, int lane)
{
    const int g = lane >> 2, t = lane & 3;
    #pragma unroll
    for (int nt = 0; nt < 6; nt++) {
        int c0 = wn * 48 + nt * 8 + 2 * t;
        #pragma unroll
        for (int mt = 0; mt < 2; mt++) {
            int rl = mt * 16 + g;
            const float* a = acc + (mt * 6 + nt) * 4;
            *(half2*)(parg + rl * PSTR + c0)       = __floats2half2_rn(a[0], a[1]);
            *(half2*)(parg + (rl + 8) * PSTR + c0) = __floats2half2_rn(a[2], a[3]);
        }
    }
}

// ---------------- rational-quadratic spline, K=8 bins ----------------
__device__ __forceinline__ float2 rq_spline(const float* __restrict__ p, float x)
{
    const float TAIL = 13.815510557964274f;
    const float INVS = 0.0625f;
    bool inside = (x >= -TAIL) && (x <= TAIL);
    float xc = fminf(fmaxf(x, -TAIL), TAIL);

    float ew[8], eh[8];
    float sw = 0.0f, sh = 0.0f;
    #pragma unroll
    for (int i = 0; i < 8; i++) {
        ew[i] = __expf(p[i] * INVS);      sw += ew[i];
        eh[i] = __expf(p[8 + i] * INVS);  sh += eh[i];
    }
    float iw = 1.0f / sw, ih = 1.0f / sh;

    float d[9]; d[0] = 1.0f; d[8] = 1.0f;
    #pragma unroll
    for (int i = 0; i < 7; i++) {
        float u = p[16 + i];
        d[i + 1] = 1e-3f + __logf(1.0f + __expf(u));   // |u| small: stable here
    }

    float cumw = 0.0f, cumh = 0.0f, cwl = -TAIL, chl = -TAIL;
    float bcwl = -TAIL, bw = 1.0f, bchl = -TAIL, bh2 = 1.0f, bd0 = 1.0f, bd1 = 1.0f;
    #pragma unroll
    for (int i = 0; i < 8; i++) {
        cumw += 1e-3f + 0.992f * (ew[i] * iw);
        cumh += 1e-3f + 0.992f * (eh[i] * ih);
        float cwr = (i == 7) ? TAIL : fmaf(2.0f * TAIL, cumw, -TAIL);
        float chr = (i == 7) ? TAIL : fmaf(2.0f * TAIL, cumh, -TAIL);
        if (xc >= cwl) { bcwl = cwl; bw = cwr - cwl; bchl = chl; bh2 = chr - chl; bd0 = d[i]; bd1 = d[i + 1]; }
        cwl = cwr; chl = chr;
    }

    float th  = (xc - bcwl) / bw;
    float th1 = th * (1.0f - th);
    float dl  = bh2 / bw;
    float den = dl + (bd0 + bd1 - 2.0f * dl) * th1;
    float y   = bchl + bh2 * (dl * th * th + bd0 * th1) / den;
    float omt = 1.0f - th;
    float ln  = dl * dl * (bd1 * th * th + 2.0f * dl * th1 + bd0 * omt * omt);
    float lad = __logf(ln) - 2.0f * __logf(den);
    float2 r; r.x = inside ? y : x; r.y = inside ? lad : 0.0f;
    return r;
}

// spline pass for one chunk: 2 features per thread (warp-private par columns)
__device__ __forceinline__ void spline_pass(int ch, const float* __restrict__ bfb,
                                            const __half* __restrict__ parg,
                                            float* __restrict__ z32, __half* __restrict__ z16,
                                            int wm, int wn, int lane, float& ldacc)
{
    const int r = wm * 32 + lane;
    #pragma unroll
    for (int q = 0; q < 2; q++) {
        int fl = 2 * wn + q;
        int f = ch * 8 + fl;
        if (f < DF) {
            float p[23];
            const float* bfp = bfb + f * 23;
            const __half* pp = parg + lane * PSTR + fl * 24;
            #pragma unroll
            for (int i = 0; i < 23; i++)
                p[i] = __half2float(pp[i]) + bfp[i];
            float xv = z32[r * Z32S + f];
            float2 yr = rq_spline(p, xv);
            z32[r * Z32S + f] = yr.x;
            z16[r * Z16S + acol(f)] = __float2half(yr.x);
            ldacc += yr.y;
        }
    }
}

// ---------------- main fused kernel ----------------
__global__ void __launch_bounds__(NTHR, 2)
maf_kernel(const float* __restrict__ x, const float* __restrict__ cond,
           const float* __restrict__ bf,
           float* __restrict__ out)
{
    extern __shared__ char smc[];
    float*  z32  = (float*)(smc + OB_Z32);    // [64][49]
    __half* z16  = (__half*)(smc + OB_Z16);   // [64][72]
    float*  ldp  = (float*)(smc + OB_LDP);    // [256]
    __half* actA = (__half*)(smc + OB_ACTA);  // [64][264]
    __half* actB = (__half*)(smc + OB_REGN);  // [64][264]; per-group halves alias par strips

    const int tid  = threadIdx.x;
    const int lane = tid & 31, w = tid >> 5;
    const int wm = w & 1, wn = w >> 1;        // group wm; within-group warp wn (0..3)
    const int barid = 1 + wm;
    const int gl = wn * 32 + lane;            // group-local thread index 0..127
    const int row0 = blockIdx.x * MROWS;
    __half* parg = (__half*)(smc + OB_REGN + wm * GHALF);   // group par strip (rows local 0..31)
    float ldacc = 0.0f;

    // group-local init (rows wm*32 .. wm*32+31)
    for (int i = gl; i < 32 * DF; i += 128) {
        int rl = i / DF, f = i - rl * DF;
        int r = wm * 32 + rl;
        z32[r * Z32S + f] = x[(row0 + r) * DF + f];
    }
    for (int i = gl; i < 32 * 64; i += 128) {
        int rl = i >> 6, f = i & 63, r = wm * 32 + rl;
        float v = (f < DF) ? x[(row0 + r) * DF + f]
                 : (f == 45) ? cond[row0 + r]
                 : (f == 46) ? 1.0f : 0.0f;
        z16[r * Z16S + acol(f)] = __float2half(v);
    }
    // ordering via dense0 entry group barrier

    for (int b = 0; b < NBLK; b++) {
        dense0(g_W0p + (size_t)b * 2 * 256 * 32, z16, actA, wm, wn, lane, barid);
        hidden_dense(g_Whp + (size_t)(b * 2 + 0) * 8 * 256 * 32, g_bhp + (b * 2 + 0) * 256,
                     actA, actB, wm, wn, lane, barid);
        hidden_dense(g_Whp + (size_t)(b * 2 + 1) * 8 * 256 * 32, g_bhp + (b * 2 + 1) * 256,
                     actB, actA, wm, wn, lane, barid);

        GBAR(barid);   // group: actB reads done (hidden2), actA writes visible -> par may alias actB
        const __half* Wfb = g_Wfp + (size_t)(b * NCHK) * 8 * FN * 32;
        const float*  bfb = bf + b * DM;

        float facc[48];
        for (int ch = 0; ch < NCHK; ch++) {
            int ns = (int)((FSL_PACK >> (4 * ch)) & 0xFu);
            // HMMA producers issued first...
            f_compute(Wfb + (size_t)ch * 8 * FN * 32, actA, wm, wn, lane, ns, facc);
            // ...previous chunk's spline overlaps their completion window
            if (ch > 0)
                spline_pass(ch - 1, bfb, parg, z32, z16, wm, wn, lane, ldacc);
            __syncwarp();    // par reads (ch-1) done across lanes before overwrite
            f_store(facc, parg, wn, lane);
            __syncwarp();    // par writes (ch) visible across lanes
        }
        spline_pass(NCHK - 1, bfb, parg, z32, z16, wm, wn, lane, ldacc);
    }

    ldp[tid] = ldacc;
    __syncthreads();
    if (tid < MROWS) {
        int l = tid & 31, wmr = tid >> 5;
        float ld = ldp[(0 * 2 + wmr) * 32 + l] + ldp[(1 * 2 + wmr) * 32 + l]
                 + ldp[(2 * 2 + wmr) * 32 + l] + ldp[(3 * 2 + wmr) * 32 + l];
        float s = 0.0f;
        #pragma unroll
        for (int f = 0; f < DF; f++) { float v = z32[tid * Z32S + f]; s = fmaf(v, v, s); }
        out[row0 + tid] = -0.5f * s - 41.35223399420827f + ld;
    }
}

// ---------------- launch ----------------
extern "C" void kernel_launch(void* const* d_in, const int* in_sizes, int n_in,
                              void* d_out, int out_size) {
    const float* x    = (const float*)d_in[0];
    const float* cond = (const float*)d_in[1];
    const float* W0   = (const float*)d_in[2];
    const float* b0   = (const float*)d_in[3];
    const float* Wc   = (const float*)d_in[4];
    const float* bc   = (const float*)d_in[5];
    const float* Wh   = (const float*)d_in[6];
    const float* bh   = (const float*)d_in[7];
    const float* Wf   = (const float*)d_in[8];
    const float* bf   = (const float*)d_in[9];
    float* out = (float*)d_out;
    const int B = in_sizes[0] / DF;

    prep_w0<<<(NBLK * 2 * 256 * 32 + 255) / 256, 256>>>(W0, Wc, b0, bc);
    prep_wh<<<(NBLK * 2 * 8 * 256 * 32 + 255) / 256, 256>>>(Wh);
    prep_wf<<<(NBLK * NCHK * 8 * FN * 32 + 255) / 256, 256>>>(Wf);
    prep_bh<<<(NBLK * 2 * 256 + 255) / 256, 256>>>(bh);

    cudaFuncSetAttribute(maf_kernel, cudaFuncAttributeMaxDynamicSharedMemorySize, SMEM_BYTES);
    maf_kernel<<<B / MROWS, NTHR, SMEM_BYTES>>>(x, cond, bf, out);
}

// round 16
// speedup vs baseline: 1.1011x; 1.0042x over previous
#include <cuda_runtime.h>
#include <cuda_fp16.h>

// ---------------- problem constants ----------------
#define NBLK 6
#define DF   45
#define DM   1035
#define MROWS 64           // rows per CTA (two independent 32-row groups)
#define NTHR 256

#define Z32S 49            // fp32 z row stride
#define Z16S 72            // fp16 z row stride (halves), 64 cols (2 k-slabs)
#define AS16 264           // fp16 act row stride (halves), 256 cols (8 k-slabs)
#define FN   192           // f-chunk cols (8 features x 24)
#define NCHK 6             // f chunks
#define PSTR 208           // fp16 params row stride (halves) -> 416B, 16B-aligned rows
#define GHALF 16896        // bytes per group half of the region (32*264*2)

// smem byte offsets (total 90368 -> 2 CTAs/SM)
#define OB_Z32  0
#define OB_Z16  12544                 // 64*49*4
#define OB_LDP  (OB_Z16 + 9216)       // [256] fp32
#define OB_ACTA (OB_LDP + 1024)
#define OB_REGN (OB_ACTA + 33792)     // actB [64][264] fp16 ALIASED with per-group par strips
#define SMEM_BYTES (OB_REGN + 33792)  // 90368

// per-N-tile k-slab bounds (degree-sorted hidden): SL[j] nibble-packed
#define SL_PACK 0x88665332u
// per-f-chunk k-slab bounds {2,3,5,6,8,8}
#define FSL_PACK 0x00886532u

#define GBAR(id) asm volatile("bar.sync %0, 128;" :: "r"(id) : "memory")

// ---------------- device weight images (masked, permuted, k-interleaved, LDG-fragment layout) ----------------
__device__ __half g_W0p[NBLK * 2 * 256 * 32];
__device__ __half g_Whp[NBLK * 2 * 8 * 256 * 32];
__device__ __half g_Wfp[NBLK * NCHK * 8 * FN * 32];
__device__ float  g_bhp[NBLK * 2 * 256];     // degree-permuted hidden biases

// ---------------- helpers ----------------
__device__ __forceinline__ void mma16(float* d, unsigned a0, unsigned a1, unsigned a2, unsigned a3,
                                      unsigned b0, unsigned b1) {
    asm volatile("mma.sync.aligned.m16n8k16.row.col.f32.f16.f16.f32 "
        "{%0,%1,%2,%3},{%4,%5,%6,%7},{%8,%9},{%0,%1,%2,%3};"
        : "+f"(d[0]), "+f"(d[1]), "+f"(d[2]), "+f"(d[3])
        : "r"(a0), "r"(a1), "r"(a2), "r"(a3), "r"(b0), "r"(b1));
}
__device__ __forceinline__ void pf_l1(const void* p) {
    asm volatile("prefetch.global.L1 [%0];" :: "l"(p));
}
// phys column of logical k within interleaved 32-k slabs (A-side layout)
__device__ __forceinline__ int acol(int c) {
    int s = c >> 5, k32 = c & 31, step = k32 >> 4, w16 = k32 & 15;
    int hi = w16 >> 3, t = (w16 & 7) >> 1, q = hi * 2 + (w16 & 1);
    return s * 32 + t * 8 + step * 4 + q;
}
// logical k from slab s, phys pos p (<32)
__device__ __forceinline__ int kfp2(int s, int p) {
    int t = p >> 3, rem = p & 7, step = rem >> 2, q = rem & 3;
    int w16 = (q < 2) ? (2 * t + q) : (8 + 2 * t + (q - 2));
    return s * 32 + step * 16 + w16;
}
// degree-sort inverse: original hidden unit for sorted index j
__device__ __forceinline__ int invp(int j) {
    return (j < 216) ? (j / 6 + 44 * (j % 6))
                     : (36 + (j - 216) / 5 + 44 * ((j - 216) % 5));
}

// ---------------- prep kernels ----------------
__global__ void prep_w0(const float* __restrict__ W0, const float* __restrict__ Wc,
                        const float* __restrict__ b0, const float* __restrict__ bc) {
    int idx = blockIdx.x * blockDim.x + threadIdx.x;
    if (idx >= NBLK * 2 * 256 * 32) return;
    int p = idx & 31, n = (idx >> 5) & 255, s = (idx >> 13) & 1, b = idx >> 14;
    int k = kfp2(s, p);
    int o = invp(n);
    float v = 0.0f;
    if (k < DF)       v = ((o % 44) >= k) ? W0[(b * 256 + o) * DF + k] : 0.0f;
    else if (k == 45) v = Wc[b * 256 + o];
    else if (k == 46) v = b0[b * 256 + o] + bc[b * 256 + o];
    g_W0p[idx] = __float2half(v);
}
__global__ void prep_wh(const float* __restrict__ Wh) {
    int idx = blockIdx.x * blockDim.x + threadIdx.x;
    if (idx >= NBLK * 2 * 8 * 256 * 32) return;
    int p = idx & 31, n = (idx >> 5) & 255, s = (idx >> 13) & 7, bl = idx >> 16;
    int o = invp(n);
    int kk = invp(kfp2(s, p));
    float v = ((o % 44) >= (kk % 44)) ? Wh[((size_t)(bl * 256 + o)) * 256 + kk] : 0.0f;
    g_Whp[idx] = __float2half(v);
}
__global__ void prep_wf(const float* __restrict__ Wf) {
    int idx = blockIdx.x * blockDim.x + threadIdx.x;
    if (idx >= NBLK * NCHK * 8 * FN * 32) return;
    int p = idx & 31, n = (idx >> 5) % FN, s = (idx / (FN * 32)) & 7;
    int ch = (idx / (FN * 32 * 8)) % NCHK, b = idx / (FN * 32 * 8 * NCHK);
    int kk = invp(kfp2(s, p));
    int fl = n / 24, i = n % 24, f = ch * 8 + fl;
    float v = 0.0f;
    if (i < 23 && f < DF && f > (kk % 44))
        v = Wf[((size_t)(b * DM + f * 23 + i)) * 256 + kk];
    g_Wfp[idx] = __float2half(v);
}
__global__ void prep_bh(const float* __restrict__ bh) {
    int idx = blockIdx.x * blockDim.x + threadIdx.x;
    if (idx >= NBLK * 2 * 256) return;
    int n = idx & 255, bl = idx >> 8;
    g_bhp[idx] = bh[bl * 256 + invp(n)];
}

// ---------------- L0 dense: [64 x 256] = z16[64 x 64] * W0[64 x 256]; group-local ----------------
__device__ __forceinline__ void dense0(const __half* __restrict__ Wg,
                                       const __half* __restrict__ z16,
                                       __half* __restrict__ dst,
                                       int wm, int wn, int lane, int barid)
{
    const int g = lane >> 2, t = lane & 3;
    const __half* bbase = Wg + ((size_t)(wn * 64 + g)) * 32 + t * 8;

    // warm L1 with slab-0 B fragments while waiting at the barrier
    #pragma unroll
    for (int nt = 0; nt < 8; nt++) pf_l1(bbase + nt * (8 * 32));

    float acc[2][8][4];
    #pragma unroll
    for (int mt = 0; mt < 2; mt++)
        #pragma unroll
        for (int nt = 0; nt < 8; nt++)
            acc[mt][nt][0] = acc[mt][nt][1] = acc[mt][nt][2] = acc[mt][nt][3] = 0.0f;

    GBAR(barid);   // entry: group's spline z16 writes / group's prior actA readers arrived

    const __half* aprow = z16 + (wm * 32 + g) * Z16S + t * 8;

    #pragma unroll
    for (int s = 0; s < 2; s++) {
        uint4 Av[4];
        {
            const __half* ap = aprow + s * 32;
            Av[0] = *(const uint4*)ap;
            Av[1] = *(const uint4*)(ap + 8 * Z16S);
            Av[2] = *(const uint4*)(ap + 16 * Z16S);
            Av[3] = *(const uint4*)(ap + 24 * Z16S);
        }
        const __half* bp = bbase + (size_t)s * (256 * 32);
        #pragma unroll
        for (int nt = 0; nt < 8; nt++) {
            uint4 Bv = *(const uint4*)(bp + nt * (8 * 32));
            mma16(acc[0][nt], Av[0].x, Av[1].x, Av[0].y, Av[1].y, Bv.x, Bv.y);
            mma16(acc[1][nt], Av[2].x, Av[3].x, Av[2].y, Av[3].y, Bv.x, Bv.y);
            mma16(acc[0][nt], Av[0].z, Av[1].z, Av[0].w, Av[1].w, Bv.z, Bv.w);
            mma16(acc[1][nt], Av[2].z, Av[3].z, Av[2].w, Av[3].w, Bv.z, Bv.w);
        }
    }
    #pragma unroll
    for (int nt = 0; nt < 8; nt++) {
        int c0 = wn * 64 + nt * 8 + 2 * t;
        int pos = acol(c0);
        #pragma unroll
        for (int mt = 0; mt < 2; mt++) {
            int r0 = wm * 32 + mt * 16 + g;
            *(half2*)(dst + r0 * AS16 + pos)       = __floats2half2_rn(acc[mt][nt][0], acc[mt][nt][1]);
            *(half2*)(dst + (r0 + 8) * AS16 + pos) = __floats2half2_rn(acc[mt][nt][2], acc[mt][nt][3]);
        }
    }
}

// ---------------- hidden dense (degree-sorted, per-warp truncated K), OUT-OF-PLACE, group-local ----------------
__device__ __forceinline__ void hidden_dense(const __half* __restrict__ Wg,
                                             const float* __restrict__ biasP,
                                             const __half* __restrict__ src,
                                             __half* __restrict__ dst,
                                             int wm, int wj, int lane, int barid)
{
    const int g = lane >> 2, t = lane & 3;

    // warm L1 with first tile's slab-0 B fragments while waiting at the barrier
    {
        const __half* pb = Wg + ((size_t)(wj * 32 + g)) * 32 + t * 8;
        #pragma unroll
        for (int j = 0; j < 4; j++) pf_l1(pb + j * (8 * 32));
    }

    float acc[2][2][4][4];
    #pragma unroll
    for (int ti = 0; ti < 2; ti++)
        #pragma unroll
        for (int mt = 0; mt < 2; mt++)
            #pragma unroll
            for (int j = 0; j < 4; j++)
                acc[ti][mt][j][0] = acc[ti][mt][j][1] = acc[ti][mt][j][2] = acc[ti][mt][j][3] = 0.0f;

    GBAR(barid);   // entry: group's src writers / group's prior dst readers arrived

    const __half* aprow = src + (wm * 32 + g) * AS16 + t * 8;

    #pragma unroll
    for (int ti = 0; ti < 2; ti++) {
        const int tile = ti ? (7 - wj) : wj;
        const int ns = (int)((SL_PACK >> (4 * tile)) & 0xFu);
        const __half* bbase = Wg + ((size_t)(tile * 32 + g)) * 32 + t * 8;
        for (int s = 0; s < ns; s++) {
            uint4 Av[4];
            {
                const __half* ap = aprow + s * 32;
                Av[0] = *(const uint4*)ap;
                Av[1] = *(const uint4*)(ap + 8 * AS16);
                Av[2] = *(const uint4*)(ap + 16 * AS16);
                Av[3] = *(const uint4*)(ap + 24 * AS16);
            }
            const __half* bp = bbase + (size_t)s * (256 * 32);
            #pragma unroll
            for (int j = 0; j < 4; j++) {
                uint4 Bv = *(const uint4*)(bp + j * (8 * 32));
                mma16(acc[ti][0][j], Av[0].x, Av[1].x, Av[0].y, Av[1].y, Bv.x, Bv.y);
                mma16(acc[ti][1][j], Av[2].x, Av[3].x, Av[2].y, Av[3].y, Bv.x, Bv.y);
                mma16(acc[ti][0][j], Av[0].z, Av[1].z, Av[0].w, Av[1].w, Bv.z, Bv.w);
                mma16(acc[ti][1][j], Av[2].z, Av[3].z, Av[2].w, Av[3].w, Bv.z, Bv.w);
            }
        }
    }
    #pragma unroll
    for (int ti = 0; ti < 2; ti++) {
        const int tile = ti ? (7 - wj) : wj;
        #pragma unroll
        for (int j = 0; j < 4; j++) {
            int c0 = tile * 32 + j * 8 + 2 * t;
            int pos = acol(c0);
            float2 bb = *(const float2*)(biasP + c0);
            #pragma unroll
            for (int mt = 0; mt < 2; mt++) {
                int r0 = wm * 32 + mt * 16 + g;
                float v0 = fmaxf(acc[ti][mt][j][0] + bb.x, 0.0f);
                float v1 = fmaxf(acc[ti][mt][j][1] + bb.y, 0.0f);
                float v2 = fmaxf(acc[ti][mt][j][2] + bb.x, 0.0f);
                float v3 = fmaxf(acc[ti][mt][j][3] + bb.y, 0.0f);
                *(half2*)(dst + r0 * AS16 + pos)       = __floats2half2_rn(v0, v1);
                *(half2*)(dst + (r0 + 8) * AS16 + pos) = __floats2half2_rn(v2, v3);
            }
        }
    }
}

// ---------------- f-layer chunk: compute (LDG+HMMA -> regs) and store split ----------------
__device__ __forceinline__ void f_compute(const __half* __restrict__ Wg,
                                          const __half* __restrict__ act,
                                          int wm, int wn, int lane, int ns,
                                          float* __restrict__ acc)   // [48] = [mt][nt][j]
{
    const int g = lane >> 2, t = lane & 3;
    #pragma unroll
    for (int i = 0; i < 48; i++) acc[i] = 0.0f;

    const __half* aprow = act + (wm * 32 + g) * AS16 + t * 8;
    const __half* bbase = Wg + ((size_t)(wn * 48 + g)) * 32 + t * 8;

    for (int s = 0; s < ns; s++) {
        uint4 Av[4];
        {
            const __half* ap = aprow + s * 32;
            Av[0] = *(const uint4*)ap;
            Av[1] = *(const uint4*)(ap + 8 * AS16);
            Av[2] = *(const uint4*)(ap + 16 * AS16);
            Av[3] = *(const uint4*)(ap + 24 * AS16);
        }
        const __half* bp = bbase + (size_t)s * (FN * 32);
        #pragma unroll
        for (int nt = 0; nt < 6; nt++) {
            uint4 Bv = *(const uint4*)(bp + nt * (8 * 32));
            mma16(acc + (0 * 6 + nt) * 4, Av[0].x, Av[1].x, Av[0].y, Av[1].y, Bv.x, Bv.y);
            mma16(acc + (1 * 6 + nt) * 4, Av[2].x, Av[3].x, Av[2].y, Av[3].y, Bv.x, Bv.y);
            mma16(acc + (0 * 6 + nt) * 4, Av[0].z, Av[1].z, Av[0].w, Av[1].w, Bv.z, Bv.w);
            mma16(acc + (1 * 6 + nt) * 4, Av[2].z, Av[3].z, Av[2].w, Av[3].w, Bv.z, Bv.w);
        }
    }
}

__device__ __forceinline__ void f_store(const float* __restrict__ acc,
                                        __half* __restrict__ parg, int wn, int lane)
{
    const int g = lane >> 2, t = lane & 3;
    #pragma unroll
    for (int nt = 0; nt < 6; nt++) {
        int c0 = wn * 48 + nt * 8 + 2 * t;
        #pragma unroll
        for (int mt = 0; mt < 2; mt++) {
            int rl = mt * 16 + g;
            const float* a = acc + (mt * 6 + nt) * 4;
            *(half2*)(parg + rl * PSTR + c0)       = __floats2half2_rn(a[0], a[1]);
            *(half2*)(parg + (rl + 8) * PSTR + c0) = __floats2half2_rn(a[2], a[3]);
        }
    }
}

// ---------------- rational-quadratic spline, K=8 bins ----------------
__device__ __forceinline__ float2 rq_spline(const float* __restrict__ p, float x)
{
    const float TAIL = 13.815510557964274f;
    const float INVS = 0.0625f;
    bool inside = (x >= -TAIL) && (x <= TAIL);
    float xc = fminf(fmaxf(x, -TAIL), TAIL);

    float ew[8], eh[8];
    float sw = 0.0f, sh = 0.0f;
    #pragma unroll
    for (int i = 0; i < 8; i++) {
        ew[i] = __expf(p[i] * INVS);      sw += ew[i];
        eh[i] = __expf(p[8 + i] * INVS);  sh += eh[i];
    }
    float iw = 1.0f / sw, ih = 1.0f / sh;

    float d[9]; d[0] = 1.0f; d[8] = 1.0f;
    #pragma unroll
    for (int i = 0; i < 7; i++) {
        float u = p[16 + i];
        d[i + 1] = 1e-3f + __logf(1.0f + __expf(u));   // |u| small: stable here
    }

    float cumw = 0.0f, cumh = 0.0f, cwl = -TAIL, chl = -TAIL;
    float bcwl = -TAIL, bw = 1.0f, bchl = -TAIL, bh2 = 1.0f, bd0 = 1.0f, bd1 = 1.0f;
    #pragma unroll
    for (int i = 0; i < 8; i++) {
        cumw += 1e-3f + 0.992f * (ew[i] * iw);
        cumh += 1e-3f + 0.992f * (eh[i] * ih);
        float cwr = (i == 7) ? TAIL : fmaf(2.0f * TAIL, cumw, -TAIL);
        float chr = (i == 7) ? TAIL : fmaf(2.0f * TAIL, cumh, -TAIL);
        if (xc >= cwl) { bcwl = cwl; bw = cwr - cwl; bchl = chl; bh2 = chr - chl; bd0 = d[i]; bd1 = d[i + 1]; }
        cwl = cwr; chl = chr;
    }

    float th  = (xc - bcwl) / bw;
    float th1 = th * (1.0f - th);
    float dl  = bh2 / bw;
    float den = dl + (bd0 + bd1 - 2.0f * dl) * th1;
    float y   = bchl + bh2 * (dl * th * th + bd0 * th1) / den;
    float omt = 1.0f - th;
    float ln  = dl * dl * (bd1 * th * th + 2.0f * dl * th1 + bd0 * omt * omt);
    float lad = __logf(ln) - 2.0f * __logf(den);
    float2 r; r.x = inside ? y : x; r.y = inside ? lad : 0.0f;
    return r;
}

// spline pass for one chunk: 2 features per thread (warp-private par columns)
__device__ __forceinline__ void spline_pass(int ch, const float* __restrict__ bfb,
                                            const __half* __restrict__ parg,
                                            float* __restrict__ z32, __half* __restrict__ z16,
                                            int wm, int wn, int lane, float& ldacc)
{
    const int r = wm * 32 + lane;
    #pragma unroll
    for (int q = 0; q < 2; q++) {
        int fl = 2 * wn + q;
        int f = ch * 8 + fl;
        if (f < DF) {
            // params: 16B-aligned strip row -> 3 x LDS.128 (24 halves, 23 used)
            union { uint4 v[3]; __half h[24]; } pb;
            const uint4* pp4 = (const uint4*)(parg + lane * PSTR + fl * 24);
            pb.v[0] = pp4[0]; pb.v[1] = pp4[1]; pb.v[2] = pp4[2];
            float p[23];
            const float* bfp = bfb + f * 23;
            #pragma unroll
            for (int i = 0; i < 23; i++)
                p[i] = __half2float(pb.h[i]) + bfp[i];
            float xv = z32[r * Z32S + f];
            float2 yr = rq_spline(p, xv);
            z32[r * Z32S + f] = yr.x;
            z16[r * Z16S + acol(f)] = __float2half(yr.x);
            ldacc += yr.y;
        }
    }
}

// ---------------- main fused kernel ----------------
__global__ void __launch_bounds__(NTHR, 2)
maf_kernel(const float* __restrict__ x, const float* __restrict__ cond,
           const float* __restrict__ bf,
           float* __restrict__ out)
{
    extern __shared__ char smc[];
    float*  z32  = (float*)(smc + OB_Z32);    // [64][49]
    __half* z16  = (__half*)(smc + OB_Z16);   // [64][72]
    float*  ldp  = (float*)(smc + OB_LDP);    // [256]
    __half* actA = (__half*)(smc + OB_ACTA);  // [64][264]
    __half* actB = (__half*)(smc + OB_REGN);  // [64][264]; per-group halves alias par strips

    const int tid  = threadIdx.x;
    const int lane = tid & 31, w = tid >> 5;
    const int wm = w & 1, wn = w >> 1;        // group wm; within-group warp wn (0..3)
    const int barid = 1 + wm;
    const int gl = wn * 32 + lane;            // group-local thread index 0..127
    const int row0 = blockIdx.x * MROWS;
    __half* parg = (__half*)(smc + OB_REGN + wm * GHALF);   // group par strip (rows local 0..31)
    float ldacc = 0.0f;

    // group-local init (rows wm*32 .. wm*32+31)
    for (int i = gl; i < 32 * DF; i += 128) {
        int rl = i / DF, f = i - rl * DF;
        int r = wm * 32 + rl;
        z32[r * Z32S + f] = x[(row0 + r) * DF + f];
    }
    for (int i = gl; i < 32 * 64; i += 128) {
        int rl = i >> 6, f = i & 63, r = wm * 32 + rl;
        float v = (f < DF) ? x[(row0 + r) * DF + f]
                 : (f == 45) ? cond[row0 + r]
                 : (f == 46) ? 1.0f : 0.0f;
        z16[r * Z16S + acol(f)] = __float2half(v);
    }
    // ordering via dense0 entry group barrier

    for (int b = 0; b < NBLK; b++) {
        dense0(g_W0p + (size_t)b * 2 * 256 * 32, z16, actA, wm, wn, lane, barid);
        hidden_dense(g_Whp + (size_t)(b * 2 + 0) * 8 * 256 * 32, g_bhp + (b * 2 + 0) * 256,
                     actA, actB, wm, wn, lane, barid);
        hidden_dense(g_Whp + (size_t)(b * 2 + 1) * 8 * 256 * 32, g_bhp + (b * 2 + 1) * 256,
                     actB, actA, wm, wn, lane, barid);

        const __half* Wfb = g_Wfp + (size_t)(b * NCHK) * 8 * FN * 32;
        const float*  bfb = bf + b * DM;

        // warm L1 with chunk-0 slab-0 B fragments before the f-phase entry barrier
        {
            const int g2 = lane >> 2, t2 = lane & 3;
            const __half* pb = Wfb + ((size_t)(wn * 48 + g2)) * 32 + t2 * 8;
            #pragma unroll
            for (int nt = 0; nt < 6; nt++) pf_l1(pb + nt * (8 * 32));
        }
        GBAR(barid);   // group: actB reads done (hidden2), actA writes visible -> par may alias actB

        float facc[48];
        for (int ch = 0; ch < NCHK; ch++) {
            int ns = (int)((FSL_PACK >> (4 * ch)) & 0xFu);
            // HMMA producers issued first...
            f_compute(Wfb + (size_t)ch * 8 * FN * 32, actA, wm, wn, lane, ns, facc);
            // ...previous chunk's spline overlaps their completion window
            if (ch > 0)
                spline_pass(ch - 1, bfb, parg, z32, z16, wm, wn, lane, ldacc);
            __syncwarp();    // par reads (ch-1) done across lanes before overwrite
            f_store(facc, parg, wn, lane);
            __syncwarp();    // par writes (ch) visible across lanes
        }
        spline_pass(NCHK - 1, bfb, parg, z32, z16, wm, wn, lane, ldacc);
    }

    ldp[tid] = ldacc;
    __syncthreads();
    if (tid < MROWS) {
        int l = tid & 31, wmr = tid >> 5;
        float ld = ldp[(0 * 2 + wmr) * 32 + l] + ldp[(1 * 2 + wmr) * 32 + l]
                 + ldp[(2 * 2 + wmr) * 32 + l] + ldp[(3 * 2 + wmr) * 32 + l];
        float s = 0.0f;
        #pragma unroll
        for (int f = 0; f < DF; f++) { float v = z32[tid * Z32S + f]; s = fmaf(v, v, s); }
        out[row0 + tid] = -0.5f * s - 41.35223399420827f + ld;
    }
}

// ---------------- launch ----------------
extern "C" void kernel_launch(void* const* d_in, const int* in_sizes, int n_in,
                              void* d_out, int out_size) {
    const float* x    = (const float*)d_in[0];
    const float* cond = (const float*)d_in[1];
    const float* W0   = (const float*)d_in[2];
    const float* b0   = (const float*)d_in[3];
    const float* Wc   = (const float*)d_in[4];
    const float* bc   = (const float*)d_in[5];
    const float* Wh   = (const float*)d_in[6];
    const float* bh   = (const float*)d_in[7];
    const float* Wf   = (const float*)d_in[8];
    const float* bf   = (const float*)d_in[9];
    float* out = (float*)d_out;
    const int B = in_sizes[0] / DF;

    prep_w0<<<(NBLK * 2 * 256 * 32 + 255) / 256, 256>>>(W0, Wc, b0, bc);
    prep_wh<<<(NBLK * 2 * 8 * 256 * 32 + 255) / 256, 256>>>(Wh);
    prep_wf<<<(NBLK * NCHK * 8 * FN * 32 + 255) / 256, 256>>>(Wf);
    prep_bh<<<(NBLK * 2 * 256 + 255) / 256, 256>>>(bh);

    cudaFuncSetAttribute(maf_kernel, cudaFuncAttributeMaxDynamicSharedMemorySize, SMEM_BYTES);
    maf_kernel<<<B / MROWS, NTHR, SMEM_BYTES>>>(x, cond, bf, out);
}

// round 17
// speedup vs baseline: 1.1758x; 1.0679x over previous
#include <cuda_runtime.h>
#include <cuda_fp16.h>

// ---------------- problem constants ----------------
#define NBLK 6
#define DF   45
#define DM   1035
#define MROWS 64           // rows per CTA (two independent 32-row groups)
#define NTHR 256

#define Z32S 49            // fp32 z row stride
#define Z16S 72            // fp16 z row stride (halves), 64 cols (2 k-slabs)
#define AS16 264           // fp16 act row stride (halves), 256 cols (8 k-slabs)
#define FN   192           // f-chunk cols (8 features x 24)
#define NCHK 6             // f chunks
#define PSTR 208           // fp16 params row stride (halves) -> 416B, 16B-aligned rows
#define GHALF 16896        // bytes per group half of the region (32*264*2)

// smem byte offsets (total 90368 -> 2 CTAs/SM)
#define OB_Z32  0
#define OB_Z16  12544                 // 64*49*4
#define OB_LDP  (OB_Z16 + 9216)       // [256] fp32
#define OB_ACTA (OB_LDP + 1024)
#define OB_REGN (OB_ACTA + 33792)     // actB [64][264] fp16 ALIASED with per-group par strips
#define SMEM_BYTES (OB_REGN + 33792)  // 90368

// per-N-tile k-slab bounds (degree-sorted hidden): SL[j] nibble-packed
#define SL_PACK 0x88665332u

#define GBAR(id) asm volatile("bar.sync %0, 128;" :: "r"(id) : "memory")

// ---------------- device weight images (masked, permuted, k-interleaved, LDG-fragment layout) ----------------
__device__ __half g_W0p[NBLK * 2 * 256 * 32];
__device__ __half g_Whp[NBLK * 2 * 8 * 256 * 32];
__device__ __half g_Wfp[NBLK * NCHK * 8 * FN * 32];
__device__ float  g_bhp[NBLK * 2 * 256];     // degree-permuted hidden biases

// ---------------- helpers ----------------
__device__ __forceinline__ void mma16(float* d, unsigned a0, unsigned a1, unsigned a2, unsigned a3,
                                      unsigned b0, unsigned b1) {
    asm volatile("mma.sync.aligned.m16n8k16.row.col.f32.f16.f16.f32 "
        "{%0,%1,%2,%3},{%4,%5,%6,%7},{%8,%9},{%0,%1,%2,%3};"
        : "+f"(d[0]), "+f"(d[1]), "+f"(d[2]), "+f"(d[3])
        : "r"(a0), "r"(a1), "r"(a2), "r"(a3), "r"(b0), "r"(b1));
}
__device__ __forceinline__ void pf_l1(const void* p) {
    asm volatile("prefetch.global.L1 [%0];" :: "l"(p));
}
// phys column of logical k within interleaved 32-k slabs (A-side layout)
__device__ __forceinline__ int acol(int c) {
    int s = c >> 5, k32 = c & 31, step = k32 >> 4, w16 = k32 & 15;
    int hi = w16 >> 3, t = (w16 & 7) >> 1, q = hi * 2 + (w16 & 1);
    return s * 32 + t * 8 + step * 4 + q;
}
// logical k from slab s, phys pos p (<32)
__device__ __forceinline__ int kfp2(int s, int p) {
    int t = p >> 3, rem = p & 7, step = rem >> 2, q = rem & 3;
    int w16 = (q < 2) ? (2 * t + q) : (8 + 2 * t + (q - 2));
    return s * 32 + step * 16 + w16;
}
// degree-sort inverse: original hidden unit for sorted index j
__device__ __forceinline__ int invp(int j) {
    return (j < 216) ? (j / 6 + 44 * (j % 6))
                     : (36 + (j - 216) / 5 + 44 * ((j - 216) % 5));
}

// ---------------- prep kernels ----------------
__global__ void prep_w0(const float* __restrict__ W0, const float* __restrict__ Wc,
                        const float* __restrict__ b0, const float* __restrict__ bc) {
    int idx = blockIdx.x * blockDim.x + threadIdx.x;
    if (idx >= NBLK * 2 * 256 * 32) return;
    int p = idx & 31, n = (idx >> 5) & 255, s = (idx >> 13) & 1, b = idx >> 14;
    int k = kfp2(s, p);
    int o = invp(n);
    float v = 0.0f;
    if (k < DF)       v = ((o % 44) >= k) ? W0[(b * 256 + o) * DF + k] : 0.0f;
    else if (k == 45) v = Wc[b * 256 + o];
    else if (k == 46) v = b0[b * 256 + o] + bc[b * 256 + o];
    g_W0p[idx] = __float2half(v);
}
__global__ void prep_wh(const float* __restrict__ Wh) {
    int idx = blockIdx.x * blockDim.x + threadIdx.x;
    if (idx >= NBLK * 2 * 8 * 256 * 32) return;
    int p = idx & 31, n = (idx >> 5) & 255, s = (idx >> 13) & 7, bl = idx >> 16;
    int o = invp(n);
    int kk = invp(kfp2(s, p));
    float v = ((o % 44) >= (kk % 44)) ? Wh[((size_t)(bl * 256 + o)) * 256 + kk] : 0.0f;
    g_Whp[idx] = __float2half(v);
}
__global__ void prep_wf(const float* __restrict__ Wf) {
    int idx = blockIdx.x * blockDim.x + threadIdx.x;
    if (idx >= NBLK * NCHK * 8 * FN * 32) return;
    int p = idx & 31, n = (idx >> 5) % FN, s = (idx / (FN * 32)) & 7;
    int ch = (idx / (FN * 32 * 8)) % NCHK, b = idx / (FN * 32 * 8 * NCHK);
    int kk = invp(kfp2(s, p));
    int fl = n / 24, i = n % 24, f = ch * 8 + fl;
    float v = 0.0f;
    if (i < 23 && f < DF && f > (kk % 44))
        v = Wf[((size_t)(b * DM + f * 23 + i)) * 256 + kk];
    g_Wfp[idx] = __float2half(v);
}
__global__ void prep_bh(const float* __restrict__ bh) {
    int idx = blockIdx.x * blockDim.x + threadIdx.x;
    if (idx >= NBLK * 2 * 256) return;
    int n = idx & 255, bl = idx >> 8;
    g_bhp[idx] = bh[bl * 256 + invp(n)];
}

// ---------------- L0 dense: [64 x 256] = z16[64 x 64] * W0[64 x 256]; group-local ----------------
__device__ __forceinline__ void dense0(const __half* __restrict__ Wg,
                                       const __half* __restrict__ z16,
                                       __half* __restrict__ dst,
                                       int wm, int wn, int lane, int barid)
{
    const int g = lane >> 2, t = lane & 3;
    const __half* bbase = Wg + ((size_t)(wn * 64 + g)) * 32 + t * 8;

    // warm L1 with slab-0 B fragments while waiting at the barrier
    #pragma unroll
    for (int nt = 0; nt < 8; nt++) pf_l1(bbase + nt * (8 * 32));

    float acc[2][8][4];
    #pragma unroll
    for (int mt = 0; mt < 2; mt++)
        #pragma unroll
        for (int nt = 0; nt < 8; nt++)
            acc[mt][nt][0] = acc[mt][nt][1] = acc[mt][nt][2] = acc[mt][nt][3] = 0.0f;

    GBAR(barid);   // entry: group's spline z16 writes / group's prior actA readers arrived

    const __half* aprow = z16 + (wm * 32 + g) * Z16S + t * 8;

    #pragma unroll
    for (int s = 0; s < 2; s++) {
        uint4 Av[4];
        {
            const __half* ap = aprow + s * 32;
            Av[0] = *(const uint4*)ap;
            Av[1] = *(const uint4*)(ap + 8 * Z16S);
            Av[2] = *(const uint4*)(ap + 16 * Z16S);
            Av[3] = *(const uint4*)(ap + 24 * Z16S);
        }
        const __half* bp = bbase + (size_t)s * (256 * 32);
        #pragma unroll
        for (int nt = 0; nt < 8; nt++) {
            uint4 Bv = *(const uint4*)(bp + nt * (8 * 32));
            mma16(acc[0][nt], Av[0].x, Av[1].x, Av[0].y, Av[1].y, Bv.x, Bv.y);
            mma16(acc[1][nt], Av[2].x, Av[3].x, Av[2].y, Av[3].y, Bv.x, Bv.y);
            mma16(acc[0][nt], Av[0].z, Av[1].z, Av[0].w, Av[1].w, Bv.z, Bv.w);
            mma16(acc[1][nt], Av[2].z, Av[3].z, Av[2].w, Av[3].w, Bv.z, Bv.w);
        }
    }
    #pragma unroll
    for (int nt = 0; nt < 8; nt++) {
        int c0 = wn * 64 + nt * 8 + 2 * t;
        int pos = acol(c0);
        #pragma unroll
        for (int mt = 0; mt < 2; mt++) {
            int r0 = wm * 32 + mt * 16 + g;
            *(half2*)(dst + r0 * AS16 + pos)       = __floats2half2_rn(acc[mt][nt][0], acc[mt][nt][1]);
            *(half2*)(dst + (r0 + 8) * AS16 + pos) = __floats2half2_rn(acc[mt][nt][2], acc[mt][nt][3]);
        }
    }
}

// ---------------- hidden dense (degree-sorted, per-warp truncated K), OUT-OF-PLACE, group-local ----------------
__device__ __forceinline__ void hidden_dense(const __half* __restrict__ Wg,
                                             const float* __restrict__ biasP,
                                             const __half* __restrict__ src,
                                             __half* __restrict__ dst,
                                             int wm, int wj, int lane, int barid)
{
    const int g = lane >> 2, t = lane & 3;

    // warm L1 with first tile's slab-0 B fragments while waiting at the barrier
    {
        const __half* pb = Wg + ((size_t)(wj * 32 + g)) * 32 + t * 8;
        #pragma unroll
        for (int j = 0; j < 4; j++) pf_l1(pb + j * (8 * 32));
    }

    float acc[2][2][4][4];
    #pragma unroll
    for (int ti = 0; ti < 2; ti++)
        #pragma unroll
        for (int mt = 0; mt < 2; mt++)
            #pragma unroll
            for (int j = 0; j < 4; j++)
                acc[ti][mt][j][0] = acc[ti][mt][j][1] = acc[ti][mt][j][2] = acc[ti][mt][j][3] = 0.0f;

    GBAR(barid);   // entry: group's src writers / group's prior dst readers arrived

    const __half* aprow = src + (wm * 32 + g) * AS16 + t * 8;

    #pragma unroll
    for (int ti = 0; ti < 2; ti++) {
        const int tile = ti ? (7 - wj) : wj;
        const int ns = (int)((SL_PACK >> (4 * tile)) & 0xFu);
        const __half* bbase = Wg + ((size_t)(tile * 32 + g)) * 32 + t * 8;
        for (int s = 0; s < ns; s++) {
            uint4 Av[4];
            {
                const __half* ap = aprow + s * 32;
                Av[0] = *(const uint4*)ap;
                Av[1] = *(const uint4*)(ap + 8 * AS16);
                Av[2] = *(const uint4*)(ap + 16 * AS16);
                Av[3] = *(const uint4*)(ap + 24 * AS16);
            }
            const __half* bp = bbase + (size_t)s * (256 * 32);
            #pragma unroll
            for (int j = 0; j < 4; j++) {
                uint4 Bv = *(const uint4*)(bp + j * (8 * 32));
                mma16(acc[ti][0][j], Av[0].x, Av[1].x, Av[0].y, Av[1].y, Bv.x, Bv.y);
                mma16(acc[ti][1][j], Av[2].x, Av[3].x, Av[2].y, Av[3].y, Bv.x, Bv.y);
                mma16(acc[ti][0][j], Av[0].z, Av[1].z, Av[0].w, Av[1].w, Bv.z, Bv.w);
                mma16(acc[ti][1][j], Av[2].z, Av[3].z, Av[2].w, Av[3].w, Bv.z, Bv.w);
            }
        }
    }
    #pragma unroll
    for (int ti = 0; ti < 2; ti++) {
        const int tile = ti ? (7 - wj) : wj;
        #pragma unroll
        for (int j = 0; j < 4; j++) {
            int c0 = tile * 32 + j * 8 + 2 * t;
            int pos = acol(c0);
            float2 bb = *(const float2*)(biasP + c0);
            #pragma unroll
            for (int mt = 0; mt < 2; mt++) {
                int r0 = wm * 32 + mt * 16 + g;
                float v0 = fmaxf(acc[ti][mt][j][0] + bb.x, 0.0f);
                float v1 = fmaxf(acc[ti][mt][j][1] + bb.y, 0.0f);
                float v2 = fmaxf(acc[ti][mt][j][2] + bb.x, 0.0f);
                float v3 = fmaxf(acc[ti][mt][j][3] + bb.y, 0.0f);
                *(half2*)(dst + r0 * AS16 + pos)       = __floats2half2_rn(v0, v1);
                *(half2*)(dst + (r0 + 8) * AS16 + pos) = __floats2half2_rn(v2, v3);
            }
        }
    }
}

// ---------------- f-layer chunk: compute (LDG+HMMA -> regs) and store split ----------------
__device__ __forceinline__ void f_compute(const __half* __restrict__ Wg,
                                          const __half* __restrict__ act,
                                          int wm, int wn, int lane, int ns,
                                          float* __restrict__ acc)   // [48] = [mt][nt][j]
{
    const int g = lane >> 2, t = lane & 3;
    #pragma unroll
    for (int i = 0; i < 48; i++) acc[i] = 0.0f;

    const __half* aprow = act + (wm * 32 + g) * AS16 + t * 8;
    const __half* bbase = Wg + ((size_t)(wn * 48 + g)) * 32 + t * 8;

    for (int s = 0; s < ns; s++) {
        uint4 Av[4];
        {
            const __half* ap = aprow + s * 32;
            Av[0] = *(const uint4*)ap;
            Av[1] = *(const uint4*)(ap + 8 * AS16);
            Av[2] = *(const uint4*)(ap + 16 * AS16);
            Av[3] = *(const uint4*)(ap + 24 * AS16);
        }
        const __half* bp = bbase + (size_t)s * (FN * 32);
        #pragma unroll
        for (int nt = 0; nt < 6; nt++) {
            uint4 Bv = *(const uint4*)(bp + nt * (8 * 32));
            mma16(acc + (0 * 6 + nt) * 4, Av[0].x, Av[1].x, Av[0].y, Av[1].y, Bv.x, Bv.y);
            mma16(acc + (1 * 6 + nt) * 4, Av[2].x, Av[3].x, Av[2].y, Av[3].y, Bv.x, Bv.y);
            mma16(acc + (0 * 6 + nt) * 4, Av[0].z, Av[1].z, Av[0].w, Av[1].w, Bv.z, Bv.w);
            mma16(acc + (1 * 6 + nt) * 4, Av[2].z, Av[3].z, Av[2].w, Av[3].w, Bv.z, Bv.w);
        }
    }
}

__device__ __forceinline__ void f_store(const float* __restrict__ acc,
                                        __half* __restrict__ parg, int wn, int lane)
{
    const int g = lane >> 2, t = lane & 3;
    #pragma unroll
    for (int nt = 0; nt < 6; nt++) {
        int c0 = wn * 48 + nt * 8 + 2 * t;
        #pragma unroll
        for (int mt = 0; mt < 2; mt++) {
            int rl = mt * 16 + g;
            const float* a = acc + (mt * 6 + nt) * 4;
            *(half2*)(parg + rl * PSTR + c0)       = __floats2half2_rn(a[0], a[1]);
            *(half2*)(parg + (rl + 8) * PSTR + c0) = __floats2half2_rn(a[2], a[3]);
        }
    }
}

// ---------------- rational-quadratic spline, K=8 bins (MUFU-free softmax/softplus) ----------------
// softmax args are p/16 (|x| << 0.1): cubic Taylor exp, err ~1e-9
// softplus arg |u| << 0.5: ln(1+e^u) = ln2 + u/2 + u^2/8 - u^4/192, err < 1e-5
__device__ __forceinline__ float2 rq_spline(const float* __restrict__ p, float x)
{
    const float TAIL = 13.815510557964274f;
    const float INVS = 0.0625f;
    bool inside = (x >= -TAIL) && (x <= TAIL);
    float xc = fminf(fmaxf(x, -TAIL), TAIL);

    float ew[8], eh[8];
    float sw = 0.0f, sh = 0.0f;
    #pragma unroll
    for (int i = 0; i < 8; i++) {
        float xw = p[i] * INVS, xh = p[8 + i] * INVS;
        float e1 = fmaf(xw, fmaf(xw, fmaf(xw, 0.16666667f, 0.5f), 1.0f), 1.0f);
        float e2 = fmaf(xh, fmaf(xh, fmaf(xh, 0.16666667f, 0.5f), 1.0f), 1.0f);
        ew[i] = e1; sw += e1;
        eh[i] = e2; sh += e2;
    }
    float iw = 1.0f / sw, ih = 1.0f / sh;

    float d[9]; d[0] = 1.0f; d[8] = 1.0f;
    #pragma unroll
    for (int i = 0; i < 7; i++) {
        float u = p[16 + i];
        float u2 = u * u;
        d[i + 1] = fmaf(u2, fmaf(u2, -5.2083333e-3f, 0.125f),
                        fmaf(u, 0.5f, 0.69414720f));   // 1e-3 + ln2 folded
    }

    float cumw = 0.0f, cumh = 0.0f, cwl = -TAIL, chl = -TAIL;
    float bcwl = -TAIL, bw = 1.0f, bchl = -TAIL, bh2 = 1.0f, bd0 = 1.0f, bd1 = 1.0f;
    #pragma unroll
    for (int i = 0; i < 8; i++) {
        cumw += 1e-3f + 0.992f * (ew[i] * iw);
        cumh += 1e-3f + 0.992f * (eh[i] * ih);
        float cwr = (i == 7) ? TAIL : fmaf(2.0f * TAIL, cumw, -TAIL);
        float chr = (i == 7) ? TAIL : fmaf(2.0f * TAIL, cumh, -TAIL);
        if (xc >= cwl) { bcwl = cwl; bw = cwr - cwl; bchl = chl; bh2 = chr - chl; bd0 = d[i]; bd1 = d[i + 1]; }
        cwl = cwr; chl = chr;
    }

    float th  = (xc - bcwl) / bw;
    float th1 = th * (1.0f - th);
    float dl  = bh2 / bw;
    float den = dl + (bd0 + bd1 - 2.0f * dl) * th1;
    float iden = 1.0f / den;
    float y   = bchl + bh2 * (dl * th * th + bd0 * th1) * iden;
    float omt = 1.0f - th;
    float ln  = dl * dl * (bd1 * th * th + 2.0f * dl * th1 + bd0 * omt * omt);
    float lad = __logf(ln * iden * iden);
    float2 r; r.x = inside ? y : x; r.y = inside ? lad : 0.0f;
    return r;
}

// spline pass for one chunk: 2 features per thread (warp-private par columns)
__device__ __forceinline__ void spline_pass(int ch, const float* __restrict__ bfb,
                                            const __half* __restrict__ parg,
                                            float* __restrict__ z32, __half* __restrict__ z16,
                                            int wm, int wn, int lane, float& ldacc)
{
    const int r = wm * 32 + lane;
    #pragma unroll
    for (int q = 0; q < 2; q++) {
        int fl = 2 * wn + q;
        int f = ch * 8 + fl;
        if (f < DF) {
            // params: 16B-aligned strip row -> 3 x LDS.128 (24 halves, 23 used)
            union { uint4 v[3]; __half h[24]; } pb;
            const uint4* pp4 = (const uint4*)(parg + lane * PSTR + fl * 24);
            pb.v[0] = pp4[0]; pb.v[1] = pp4[1]; pb.v[2] = pp4[2];
            float p[23];
            const float* bfp = bfb + f * 23;
            #pragma unroll
            for (int i = 0; i < 23; i++)
                p[i] = __half2float(pb.h[i]) + bfp[i];
            float xv = z32[r * Z32S + f];
            float2 yr = rq_spline(p, xv);
            z32[r * Z32S + f] = yr.x;
            z16[r * Z16S + acol(f)] = __float2half(yr.x);
            ldacc += yr.y;
        }
    }
}

// ---------------- main fused kernel ----------------
__global__ void __launch_bounds__(NTHR, 2)
maf_kernel(const float* __restrict__ x, const float* __restrict__ cond,
           const float* __restrict__ bf,
           float* __restrict__ out)
{
    extern __shared__ char smc[];
    float*  z32  = (float*)(smc + OB_Z32);    // [64][49]
    __half* z16  = (__half*)(smc + OB_Z16);   // [64][72]
    float*  ldp  = (float*)(smc + OB_LDP);    // [256]
    __half* actA = (__half*)(smc + OB_ACTA);  // [64][264]
    __half* actB = (__half*)(smc + OB_REGN);  // [64][264]; per-group halves alias par strips

    const int tid  = threadIdx.x;
    const int lane = tid & 31, w = tid >> 5;
    const int wm = w & 1, wn = w >> 1;        // group wm; within-group warp wn (0..3)
    const int barid = 1 + wm;
    const int gl = wn * 32 + lane;            // group-local thread index 0..127
    const int row0 = blockIdx.x * MROWS;
    __half* parg = (__half*)(smc + OB_REGN + wm * GHALF);   // group par strip (rows local 0..31)
    float ldacc = 0.0f;

    // per-warp f-phase slab bounds: nibble ch of fslw = slabs needed by this warp's 2 features
    const unsigned fslw = (wn == 0) ? 0x875421u : (wn == 3) ? 0x086532u : 0x876431u;

    // group-local init (rows wm*32 .. wm*32+31)
    for (int i = gl; i < 32 * DF; i += 128) {
        int rl = i / DF, f = i - rl * DF;
        int r = wm * 32 + rl;
        z32[r * Z32S + f] = x[(row0 + r) * DF + f];
    }
    for (int i = gl; i < 32 * 64; i += 128) {
        int rl = i >> 6, f = i & 63, r = wm * 32 + rl;
        float v = (f < DF) ? x[(row0 + r) * DF + f]
                 : (f == 45) ? cond[row0 + r]
                 : (f == 46) ? 1.0f : 0.0f;
        z16[r * Z16S + acol(f)] = __float2half(v);
    }
    // ordering via dense0 entry group barrier

    for (int b = 0; b < NBLK; b++) {
        dense0(g_W0p + (size_t)b * 2 * 256 * 32, z16, actA, wm, wn, lane, barid);
        hidden_dense(g_Whp + (size_t)(b * 2 + 0) * 8 * 256 * 32, g_bhp + (b * 2 + 0) * 256,
                     actA, actB, wm, wn, lane, barid);
        hidden_dense(g_Whp + (size_t)(b * 2 + 1) * 8 * 256 * 32, g_bhp + (b * 2 + 1) * 256,
                     actB, actA, wm, wn, lane, barid);

        const __half* Wfb = g_Wfp + (size_t)(b * NCHK) * 8 * FN * 32;
        const float*  bfb = bf + b * DM;

        // warm L1 with chunk-0 slab-0 B fragments before the f-phase entry barrier
        {
            const int g2 = lane >> 2, t2 = lane & 3;
            const __half* pb = Wfb + ((size_t)(wn * 48 + g2)) * 32 + t2 * 8;
            #pragma unroll
            for (int nt = 0; nt < 6; nt++) pf_l1(pb + nt * (8 * 32));
        }
        GBAR(barid);   // group: actB reads done (hidden2), actA writes visible -> par may alias actB

        float facc[48];
        for (int ch = 0; ch < NCHK; ch++) {
            int ns = (int)((fslw >> (4 * ch)) & 0xFu);
            // HMMA producers issued first...
            f_compute(Wfb + (size_t)ch * 8 * FN * 32, actA, wm, wn, lane, ns, facc);
            // ...previous chunk's spline overlaps their completion window
            if (ch > 0)
                spline_pass(ch - 1, bfb, parg, z32, z16, wm, wn, lane, ldacc);
            __syncwarp();    // par reads (ch-1) done across lanes before overwrite
            f_store(facc, parg, wn, lane);
            __syncwarp();    // par writes (ch) visible across lanes
        }
        spline_pass(NCHK - 1, bfb, parg, z32, z16, wm, wn, lane, ldacc);
    }

    ldp[tid] = ldacc;
    __syncthreads();
    if (tid < MROWS) {
        int l = tid & 31, wmr = tid >> 5;
        float ld = ldp[(0 * 2 + wmr) * 32 + l] + ldp[(1 * 2 + wmr) * 32 + l]
                 + ldp[(2 * 2 + wmr) * 32 + l] + ldp[(3 * 2 + wmr) * 32 + l];
        float s = 0.0f;
        #pragma unroll
        for (int f = 0; f < DF; f++) { float v = z32[tid * Z32S + f]; s = fmaf(v, v, s); }
        out[row0 + tid] = -0.5f * s - 41.35223399420827f + ld;
    }
}

// ---------------- launch ----------------
extern "C" void kernel_launch(void* const* d_in, const int* in_sizes, int n_in,
                              void* d_out, int out_size) {
    const float* x    = (const float*)d_in[0];
    const float* cond = (const float*)d_in[1];
    const float* W0   = (const float*)d_in[2];
    const float* b0   = (const float*)d_in[3];
    const float* Wc   = (const float*)d_in[4];
    const float* bc   = (const float*)d_in[5];
    const float* Wh   = (const float*)d_in[6];
    const float* bh   = (const float*)d_in[7];
    const float* Wf   = (const float*)d_in[8];
    const float* bf   = (const float*)d_in[9];
    float* out = (float*)d_out;
    const int B = in_sizes[0] / DF;

    prep_w0<<<(NBLK * 2 * 256 * 32 + 255) / 256, 256>>>(W0, Wc, b0, bc);
    prep_wh<<<(NBLK * 2 * 8 * 256 * 32 + 255) / 256, 256>>>(Wh);
    prep_wf<<<(NBLK * NCHK * 8 * FN * 32 + 255) / 256, 256>>>(Wf);
    prep_bh<<<(NBLK * 2 * 256 + 255) / 256, 256>>>(bh);

    cudaFuncSetAttribute(maf_kernel, cudaFuncAttributeMaxDynamicSharedMemorySize, SMEM_BYTES);
    maf_kernel<<<B / MROWS, NTHR, SMEM_BYTES>>>(x, cond, bf, out);
}